// round 14
// baseline (speedup 1.0000x reference)
#include <cuda_runtime.h>

// Problem constants (fixed by reference_code)
#define LSEQ 8192
#define BATCH 32
#define CIN 7
#define KER 73            // 512 // 7
#define DM 512
#define RT 8              // output rows per tile
#define SL 256            // rows per block strip (proven shape)
#define TILES (SL / RT)   // 32
#define WROWS (SL + 16 + 1)    // 273 window rows: strip + 16 back + 1 fwd
#define WSRC (WROWS * CIN)     // 1911 staged elements
#define XPITCH 276             // row pitch: >=273, 16B-aligned

// out[b, n, c*73+k] = conv_b[k] + sum_{j=0..17} W2[k][j] * x[b, n+1-j, c]
//   W2[k][j] = conv_w[k][ (j/3)*3 + (2 - j%3) ]
// Conv position p = n-1+t contributes only if (after circular wrap) p >= 15.
// Interior rows 16..L-2 are unconditionally valid (fast path).
//
// (512, 3): R10-proven config — 42-reg cap, no spill, occ 64%. R12 proved 32
// regs spills; R13 proved warp-staggered tile order costs ALU. This round:
// strip-level fast branch (branch-free inner loop) + unroll 2 so ptxas can
// overlap tile t+1's LDS.128 batch under tile t's FMA tail and stores.

__global__ __launch_bounds__(512, 3)
void tokemb_kernel(const float* __restrict__ x,
                   const float* __restrict__ conv_w,
                   const float* __restrict__ conv_b,
                   const float* __restrict__ left_w,
                   const float* __restrict__ left_b,
                   float* __restrict__ out)
{
    const int d  = threadIdx.x;          // output channel 0..511
    const int s0 = blockIdx.x * SL;      // strip start row
    const int b  = blockIdx.y;

    // Per-thread channel / weights / bias (loaded ONCE per block)
    const bool main_ch = (d < CIN * KER);            // d < 511
    const int  c    = main_ch ? (d / KER) : (CIN - 1);
    const float* wsrc = main_ch ? (conv_w + (d % KER) * 18) : left_w;
    const float bias  = main_ch ? conv_b[d % KER] : left_b[0];

    float w[18];
    #pragma unroll
    for (int j = 0; j < 18; ++j)
        w[j] = wsrc[(j / 3) * 3 + 2 - (j % 3)];

    const float* xb = x + (size_t)b * LSEQ * CIN;

    // Stage x[b, s0-16 .. s0+SL, :] TRANSPOSED: xs[c][row], row-contiguous so
    // tile reads vectorize to LDS.128. Index-clamped; clamped junk rows are
    // only consumed by slow-path tiles, which bypass smem entirely.
    __shared__ float xs[CIN][XPITCH];
    {
        const int gbase = (s0 - 16) * CIN;   // may be negative at strip 0
        for (int idx = d; idx < WSRC; idx += 512) {
            int g = gbase + idx;
            g = min(max(g, 0), LSEQ * CIN - 1);
            const int row = idx / CIN;
            const int cc  = idx - row * CIN;
            xs[cc][row] = xb[g];
        }
    }
    __syncthreads();

    float* outp = out + ((size_t)(b * LSEQ + s0)) * DM + d;

    // Strip-level uniform branch: 1022/1024 blocks are entirely fast-path.
    if ((s0 >= 16) && (s0 + SL <= LSEQ - 1)) {
        #pragma unroll 2
        for (int t = 0; t < TILES; ++t) {
            // xs[c] row l = global row s0-16+l; tile t reads rows t*8..t*8+24
            const float*  xcol = &xs[c][t * RT];            // t*8 % 4 == 0
            const float4* xq   = reinterpret_cast<const float4*>(xcol);
            float* op = outp + t * RT * DM;

            float acc[RT];

            // Value-outer fanout with vector loads. Tap j feeds output row
            // nl = i + j - 17; ascending i makes j==17 the first writer of
            // each acc -> fold bias init into it (i == nl, j == 17).
            #pragma unroll
            for (int g4 = 0; g4 < 6; ++g4) {
                const float4 q = xq[g4];             // LDS.128: i = 4g..4g+3
                const float qv[4] = {q.x, q.y, q.z, q.w};
                #pragma unroll
                for (int c4 = 0; c4 < 4; ++c4) {
                    const int   i  = 4 * g4 + c4;
                    const float xv = qv[c4];
                    #pragma unroll
                    for (int j = 0; j < 18; ++j) {
                        const int nl = i + j - 17;
                        if (nl >= 0 && nl < RT) {
                            if (j == 17) acc[nl] = fmaf(w[17], xv, bias);
                            else         acc[nl] = fmaf(w[j],  xv, acc[nl]);
                        }
                    }
                }
            }
            {   // window value i = 24: only tap j=0 (nl = 7) remains
                acc[RT - 1] = fmaf(w[0], xcol[24], acc[RT - 1]);
            }

            #pragma unroll
            for (int nl = 0; nl < RT; ++nl)
                op[nl * DM] = acc[nl];
        }
    } else {
        // Generic strip: explicit wrap + validity per conv tap. Only the
        // first and last strip of each sequence (64/1024 blocks) land here.
        for (int nl = 0; nl < SL; ++nl) {
            const int n = s0 + nl;
            float acc = bias;
            #pragma unroll
            for (int tt = 0; tt < 3; ++tt) {
                int p = n - 1 + tt;
                if (p < 0)      p += LSEQ;   // circular pad left
                if (p >= LSEQ)  p -= LSEQ;   // circular pad right
                if (p >= 15) {               // delay-embedding validity
                    #pragma unroll
                    for (int m = 0; m < 6; ++m)
                        acc = fmaf(w[3 * m + 2 - tt],
                                   xb[(p - 3 * m) * CIN + c], acc);
                }
            }
            outp[nl * DM] = acc;
        }
    }
}

extern "C" void kernel_launch(void* const* d_in, const int* in_sizes, int n_in,
                              void* d_out, int out_size)
{
    const float* x      = (const float*)d_in[0];
    const float* conv_w = (const float*)d_in[1];
    const float* conv_b = (const float*)d_in[2];
    const float* left_w = (const float*)d_in[3];
    const float* left_b = (const float*)d_in[4];
    float* out = (float*)d_out;

    dim3 grid(LSEQ / SL, BATCH);   // (32, 32) = 1024 blocks
    tokemb_kernel<<<grid, 512>>>(x, conv_w, conv_b, left_w, left_b, out);
}

// round 15
// speedup vs baseline: 1.0699x; 1.0699x over previous
#include <cuda_runtime.h>

// Problem constants (fixed by reference_code)
#define LSEQ 8192
#define BATCH 32
#define CIN 7
#define KER 73            // 512 // 7
#define DM 512
#define RT 8              // output rows per tile
#define SL 256            // rows per block strip (proven shape)
#define TILES (SL / RT)   // 32
#define WROWS (SL + 16 + 1)    // 273 window rows: strip + 16 back + 1 fwd
#define WSRC (WROWS * CIN)     // 1911 staged elements
#define XPITCH 276             // row pitch: >=273, 16B-aligned

// out[b, n, c*73+k] = conv_b[k] + sum_{j=0..17} W2[k][j] * x[b, n+1-j, c]
//   W2[k][j] = conv_w[k][ (j/3)*3 + (2 - j%3) ]
// Conv position p = n-1+t contributes only if (after circular wrap) p >= 15.
// Interior rows 16..L-2 are unconditionally valid (fast path).
//
// (512, 3): R10-proven config — 42-reg cap, regs=40, no spill, occ 64%.
// Hard-won constraints: 32-reg cap spills (R12); warp stagger costs ALU (R13);
// unroll 2 under the reg cap collapses the schedule (R14: 370us). This round
// is R10 + strip-level branch hoist ONLY, tile loop pinned at unroll 1.

__global__ __launch_bounds__(512, 3)
void tokemb_kernel(const float* __restrict__ x,
                   const float* __restrict__ conv_w,
                   const float* __restrict__ conv_b,
                   const float* __restrict__ left_w,
                   const float* __restrict__ left_b,
                   float* __restrict__ out)
{
    const int d  = threadIdx.x;          // output channel 0..511
    const int s0 = blockIdx.x * SL;      // strip start row
    const int b  = blockIdx.y;

    // Per-thread channel / weights / bias (loaded ONCE per block)
    const bool main_ch = (d < CIN * KER);            // d < 511
    const int  c    = main_ch ? (d / KER) : (CIN - 1);
    const float* wsrc = main_ch ? (conv_w + (d % KER) * 18) : left_w;
    const float bias  = main_ch ? conv_b[d % KER] : left_b[0];

    float w[18];
    #pragma unroll
    for (int j = 0; j < 18; ++j)
        w[j] = wsrc[(j / 3) * 3 + 2 - (j % 3)];

    const float* xb = x + (size_t)b * LSEQ * CIN;

    // Stage x[b, s0-16 .. s0+SL, :] TRANSPOSED: xs[c][row], row-contiguous so
    // tile reads vectorize to LDS.128. Index-clamped; clamped junk rows are
    // only consumed by slow-path strips, which bypass smem entirely.
    __shared__ float xs[CIN][XPITCH];
    {
        const int gbase = (s0 - 16) * CIN;   // may be negative at strip 0
        for (int idx = d; idx < WSRC; idx += 512) {
            int g = gbase + idx;
            g = min(max(g, 0), LSEQ * CIN - 1);
            const int row = idx / CIN;
            const int cc  = idx - row * CIN;
            xs[cc][row] = xb[g];
        }
    }
    __syncthreads();

    float* outp = out + ((size_t)(b * LSEQ + s0)) * DM + d;

    // Strip-level uniform branch: 1022/1024 blocks are entirely fast-path,
    // so the inner tile loop carries no branch at all.
    if ((s0 >= 16) && (s0 + SL <= LSEQ - 1)) {
        #pragma unroll 1
        for (int t = 0; t < TILES; ++t) {
            // xs[c] row l = global row s0-16+l; tile t reads rows t*8..t*8+24
            const float*  xcol = &xs[c][t * RT];            // t*8 % 4 == 0
            const float4* xq   = reinterpret_cast<const float4*>(xcol);
            float* op = outp + t * RT * DM;

            float acc[RT];

            // Value-outer fanout with vector loads. Tap j feeds output row
            // nl = i + j - 17; ascending i makes j==17 the first writer of
            // each acc -> fold bias init into it (i == nl, j == 17).
            #pragma unroll
            for (int g4 = 0; g4 < 6; ++g4) {
                const float4 q = xq[g4];             // LDS.128: i = 4g..4g+3
                const float qv[4] = {q.x, q.y, q.z, q.w};
                #pragma unroll
                for (int c4 = 0; c4 < 4; ++c4) {
                    const int   i  = 4 * g4 + c4;
                    const float xv = qv[c4];
                    #pragma unroll
                    for (int j = 0; j < 18; ++j) {
                        const int nl = i + j - 17;
                        if (nl >= 0 && nl < RT) {
                            if (j == 17) acc[nl] = fmaf(w[17], xv, bias);
                            else         acc[nl] = fmaf(w[j],  xv, acc[nl]);
                        }
                    }
                }
            }
            {   // window value i = 24: only tap j=0 (nl = 7) remains
                acc[RT - 1] = fmaf(w[0], xcol[24], acc[RT - 1]);
            }

            #pragma unroll
            for (int nl = 0; nl < RT; ++nl)
                op[nl * DM] = acc[nl];
        }
    } else {
        // Generic strip: explicit wrap + validity per conv tap. Only the
        // first and last strip of each sequence (64/1024 blocks) land here.
        for (int nl = 0; nl < SL; ++nl) {
            const int n = s0 + nl;
            float acc = bias;
            #pragma unroll
            for (int tt = 0; tt < 3; ++tt) {
                int p = n - 1 + tt;
                if (p < 0)      p += LSEQ;   // circular pad left
                if (p >= LSEQ)  p -= LSEQ;   // circular pad right
                if (p >= 15) {               // delay-embedding validity
                    #pragma unroll
                    for (int m = 0; m < 6; ++m)
                        acc = fmaf(w[3 * m + 2 - tt],
                                   xb[(p - 3 * m) * CIN + c], acc);
                }
            }
            outp[nl * DM] = acc;
        }
    }
}

extern "C" void kernel_launch(void* const* d_in, const int* in_sizes, int n_in,
                              void* d_out, int out_size)
{
    const float* x      = (const float*)d_in[0];
    const float* conv_w = (const float*)d_in[1];
    const float* conv_b = (const float*)d_in[2];
    const float* left_w = (const float*)d_in[3];
    const float* left_b = (const float*)d_in[4];
    float* out = (float*)d_out;

    dim3 grid(LSEQ / SL, BATCH);   // (32, 32) = 1024 blocks
    tokemb_kernel<<<grid, 512>>>(x, conv_w, conv_b, left_w, left_b, out);
}

// round 16
// speedup vs baseline: 3.3942x; 3.1723x over previous
#include <cuda_runtime.h>

// Problem constants (fixed by reference_code)
#define LSEQ 8192
#define BATCH 32
#define CIN 7
#define KER 73            // 512 // 7
#define DM 512
#define RT 8              // output rows per tile
#define SL 256            // rows per block strip (proven shape)
#define TILES (SL / RT)   // 32
#define WROWS (SL + 16 + 1)    // 273 window rows: strip + 16 back + 1 fwd
#define WSRC (WROWS * CIN)     // 1911 staged elements
#define XPITCH 276             // row pitch: >=273, 16B-aligned

// out[b, n, c*73+k] = conv_b[k] + sum_{j=0..17} W2[k][j] * x[b, n+1-j, c]
//   W2[k][j] = conv_w[k][ (j/3)*3 + (2 - j%3) ]
// Conv position p = n-1+t contributes only if (after circular wrap) p >= 15.
// Interior rows 16..L-2 are unconditionally valid (fast path).
//
// Hard-won constraints: 32-reg cap spills (R12); warp stagger costs ALU (R13);
// unroll 2 collapses the schedule (R14); sending WHOLE strips down the
// generic path creates straggler blocks that gate the kernel (R14/R15:
// 370/346us). => generic work stays at TILE granularity; fast strips get a
// branch-free loop; boundary strips use per-tile dispatch (R10 behavior).

__device__ __forceinline__ void fast_tile(const float* __restrict__ xcol,
                                          const float* __restrict__ w,
                                          float bias,
                                          float* __restrict__ op)
{
    const float4* xq = reinterpret_cast<const float4*>(xcol);  // 16B-aligned
    float acc[RT];

    // Value-outer fanout with vector loads. Tap j feeds output row
    // nl = i + j - 17; ascending i makes j==17 the first writer of each
    // acc -> fold bias init into it (i == nl, j == 17).
    #pragma unroll
    for (int g4 = 0; g4 < 6; ++g4) {
        const float4 q = xq[g4];                 // LDS.128: i = 4g..4g+3
        const float qv[4] = {q.x, q.y, q.z, q.w};
        #pragma unroll
        for (int c4 = 0; c4 < 4; ++c4) {
            const int   i  = 4 * g4 + c4;
            const float xv = qv[c4];
            #pragma unroll
            for (int j = 0; j < 18; ++j) {
                const int nl = i + j - 17;
                if (nl >= 0 && nl < RT) {
                    if (j == 17) acc[nl] = fmaf(w[17], xv, bias);
                    else         acc[nl] = fmaf(w[j],  xv, acc[nl]);
                }
            }
        }
    }
    // window value i = 24: only tap j=0 (nl = 7) remains
    acc[RT - 1] = fmaf(w[0], xcol[24], acc[RT - 1]);

    #pragma unroll
    for (int nl = 0; nl < RT; ++nl)
        op[nl * DM] = acc[nl];
}

__global__ __launch_bounds__(512, 3)
void tokemb_kernel(const float* __restrict__ x,
                   const float* __restrict__ conv_w,
                   const float* __restrict__ conv_b,
                   const float* __restrict__ left_w,
                   const float* __restrict__ left_b,
                   float* __restrict__ out)
{
    const int d  = threadIdx.x;          // output channel 0..511
    const int s0 = blockIdx.x * SL;      // strip start row
    const int b  = blockIdx.y;

    // Per-thread channel / weights / bias (loaded ONCE per block)
    const bool main_ch = (d < CIN * KER);            // d < 511
    const int  c    = main_ch ? (d / KER) : (CIN - 1);
    const float* wsrc = main_ch ? (conv_w + (d % KER) * 18) : left_w;
    const float bias  = main_ch ? conv_b[d % KER] : left_b[0];

    float w[18];
    #pragma unroll
    for (int j = 0; j < 18; ++j)
        w[j] = wsrc[(j / 3) * 3 + 2 - (j % 3)];

    const float* xb = x + (size_t)b * LSEQ * CIN;

    // Stage x[b, s0-16 .. s0+SL, :] TRANSPOSED: xs[c][row], row-contiguous so
    // tile reads vectorize to LDS.128. Index-clamped; clamped junk rows are
    // only consumed by generic tiles, which bypass smem entirely.
    __shared__ float xs[CIN][XPITCH];
    {
        const int gbase = (s0 - 16) * CIN;   // may be negative at strip 0
        for (int idx = d; idx < WSRC; idx += 512) {
            int g = gbase + idx;
            g = min(max(g, 0), LSEQ * CIN - 1);
            const int row = idx / CIN;
            const int cc  = idx - row * CIN;
            xs[cc][row] = xb[g];
        }
    }
    __syncthreads();

    float* outp = out + ((size_t)(b * LSEQ + s0)) * DM + d;

    if ((s0 >= 16) && (s0 + SL <= LSEQ - 1)) {
        // 1022/1024 blocks: branch-free tile loop, exactly one tile in flight.
        #pragma unroll 1
        for (int t = 0; t < TILES; ++t)
            fast_tile(&xs[c][t * RT], w, bias, outp + t * RT * DM);
    } else {
        // Boundary strips: per-tile dispatch (R10 behavior). Interior tiles
        // still take the fast body; only <=3 tiles per sequence go generic.
        #pragma unroll 1
        for (int t = 0; t < TILES; ++t) {
            const int n0 = s0 + t * RT;
            float* op = outp + t * RT * DM;

            if ((n0 >= 16) && (n0 + RT <= LSEQ - 1)) {
                fast_tile(&xs[c][t * RT], w, bias, op);
            } else {
                // Generic tile: explicit wrap + validity per conv tap.
                for (int nl = 0; nl < RT; ++nl) {
                    const int n = n0 + nl;
                    float acc = bias;
                    #pragma unroll
                    for (int tt = 0; tt < 3; ++tt) {
                        int p = n - 1 + tt;
                        if (p < 0)      p += LSEQ;   // circular pad left
                        if (p >= LSEQ)  p -= LSEQ;   // circular pad right
                        if (p >= 15) {               // delay-embedding validity
                            #pragma unroll
                            for (int m = 0; m < 6; ++m)
                                acc = fmaf(w[3 * m + 2 - tt],
                                           xb[(p - 3 * m) * CIN + c], acc);
                        }
                    }
                    op[nl * DM] = acc;
                }
            }
        }
    }
}

extern "C" void kernel_launch(void* const* d_in, const int* in_sizes, int n_in,
                              void* d_out, int out_size)
{
    const float* x      = (const float*)d_in[0];
    const float* conv_w = (const float*)d_in[1];
    const float* conv_b = (const float*)d_in[2];
    const float* left_w = (const float*)d_in[3];
    const float* left_b = (const float*)d_in[4];
    float* out = (float*)d_out;

    dim3 grid(LSEQ / SL, BATCH);   // (32, 32) = 1024 blocks
    tokemb_kernel<<<grid, 512>>>(x, conv_w, conv_b, left_w, left_b, out);
}